// round 15
// baseline (speedup 1.0000x reference)
#include <cuda_runtime.h>

// DisentangledSelfAttention, fused fp32, occupancy v2 + algebraic GEMM fusion.
// Precompute kernel: g_MT[h][c][e] = M_h[e][c], M_h = Wq_h @ Wk_h^T  (E x E,
// batch-independent). Main kernel (1 batch/CTA, 128 thr, ~53.5KB smem -> 4
// CTAs/SM): per head KM = k@M^T, scores = q@KM^T - mqKM (centering folded
// into column init), softmax, Vh = v@Wv, out = attn@Vh + q@Wr + br + u@Vh.
// bq/bk cancel (centering / softmax invariance); unary is rank-1 -> epilogue.

#define LDW  68   // staging + scores stride (float4, conflict-free)
#define LDKV 66   // KMT/Vh stride (float2, 4-way store conflicts only)

#define O_A   0                     // staging: MT / Wv / Wr
#define O_C   (O_A + 64 * LDW)      // scores / attn
#define O_B   (O_C + 64 * LDW)      // KMT, then Vh
#define O_MQ  (O_B + 64 * LDKV)     // [64]
#define O_MQK (O_MQ + 64)           // [64] mqKM
#define O_UV  (O_MQK + 64)          // [64] u@Vh
#define O_USM (O_UV + 64)           // [4][64]
#define SM_FLOATS (O_USM + 256)     // 13376 floats = 53504 B

__device__ float g_MT[4 * 64 * 64];   // [h][c][e] = M_h[e][c]

__global__ __launch_bounds__(256) void precompute_MT(const float* __restrict__ Wq,
                                                     const float* __restrict__ Wk) {
    __shared__ float sq[64 * 68], sk[64 * 68];
    const int h = blockIdx.x, hc = h << 6, tid = threadIdx.x;
#pragma unroll
    for (int it = 0; it < 4; it++) {
        int i = tid + (it << 8);
        int e = i >> 4, a = (i & 15) << 2;
        *(float4*)&sq[e * 68 + a] = *(const float4*)&Wq[(e << 8) + hc + a];
        *(float4*)&sk[e * 68 + a] = *(const float4*)&Wk[(e << 8) + hc + a];
    }
    __syncthreads();
#pragma unroll
    for (int it = 0; it < 16; it++) {
        int idx = tid + (it << 8);
        int c = idx >> 6, e = idx & 63;
        float acc = 0.0f;
#pragma unroll
        for (int a = 0; a < 64; a += 4) {
            float4 qa = *(const float4*)&sq[e * 68 + a];
            float4 ka = *(const float4*)&sk[c * 68 + a];
            acc = fmaf(qa.x, ka.x, acc);
            acc = fmaf(qa.y, ka.y, acc);
            acc = fmaf(qa.z, ka.z, acc);
            acc = fmaf(qa.w, ka.w, acc);
        }
        g_MT[(h << 12) + (c << 6) + e] = acc;   // MT[c][e] = M[e][c]
    }
}

// A (global or smem, stride lda) x B (smem, stride ldb, float4 reads).
__device__ __forceinline__ void gemm4(const float* __restrict__ A, int lda,
                                      const float* __restrict__ B, int ldb,
                                      float acc[8][4], int R, int C) {
#pragma unroll
    for (int k = 0; k < 64; k += 4) {
        float4 a[8];
#pragma unroll
        for (int i = 0; i < 8; i++)
            a[i] = *(const float4*)&A[(R + i) * lda + k];
#pragma unroll
        for (int kk = 0; kk < 4; kk++) {
            float4 b4 = *(const float4*)&B[(k + kk) * ldb + C];
#pragma unroll
            for (int i = 0; i < 8; i++) {
                float av = (kk == 0) ? a[i].x : (kk == 1) ? a[i].y
                         : (kk == 2) ? a[i].z : a[i].w;
                acc[i][0] = fmaf(av, b4.x, acc[i][0]);
                acc[i][1] = fmaf(av, b4.y, acc[i][1]);
                acc[i][2] = fmaf(av, b4.z, acc[i][2]);
                acc[i][3] = fmaf(av, b4.w, acc[i][3]);
            }
        }
    }
}

// A (global or smem, stride lda, float4) x B (smem, stride ldb even, float2).
__device__ __forceinline__ void gemm2(const float* __restrict__ A, int lda,
                                      const float* __restrict__ B, int ldb,
                                      float acc[8][4], int R, int C) {
#pragma unroll
    for (int k = 0; k < 64; k += 4) {
        float4 a[8];
#pragma unroll
        for (int i = 0; i < 8; i++) a[i] = *(const float4*)&A[(R + i) * lda + k];
#pragma unroll
        for (int kk = 0; kk < 4; kk++) {
            float2 bl = *(const float2*)&B[(k + kk) * ldb + C];
            float2 bh = *(const float2*)&B[(k + kk) * ldb + C + 2];
#pragma unroll
            for (int i = 0; i < 8; i++) {
                float av = (kk == 0) ? a[i].x : (kk == 1) ? a[i].y
                         : (kk == 2) ? a[i].z : a[i].w;
                acc[i][0] = fmaf(av, bl.x, acc[i][0]);
                acc[i][1] = fmaf(av, bl.y, acc[i][1]);
                acc[i][2] = fmaf(av, bh.x, acc[i][2]);
                acc[i][3] = fmaf(av, bh.y, acc[i][3]);
            }
        }
    }
}

__device__ __forceinline__ void init_tile(float acc[8][4], float v0, float v1,
                                          float v2, float v3) {
#pragma unroll
    for (int i = 0; i < 8; i++) {
        acc[i][0] = v0; acc[i][1] = v1; acc[i][2] = v2; acc[i][3] = v3;
    }
}

__device__ __forceinline__ void store_w(float* __restrict__ dst,
                                        float acc[8][4], int R, int C) {
#pragma unroll
    for (int i = 0; i < 8; i++)
        *(float4*)&dst[(R + i) * LDW + C] =
            make_float4(acc[i][0], acc[i][1], acc[i][2], acc[i][3]);
}

// dst[e*LDW + c] = W[e*256 + hc + c]; 128 threads.
__device__ __forceinline__ void stage_w(float* __restrict__ dst,
                                        const float* __restrict__ W,
                                        int hc, int tid) {
#pragma unroll
    for (int it = 0; it < 8; it++) {
        int i = tid + (it << 7);
        int e = i >> 4, c = (i & 15) << 2;
        *(float4*)&dst[e * LDW + c] = *(const float4*)&W[(e << 8) + hc + c];
    }
}

// dst[c*LDW + e] = g_MT[h][c][e]; 128 threads.
__device__ __forceinline__ void stage_mt(float* __restrict__ dst, int h, int tid) {
#pragma unroll
    for (int it = 0; it < 8; it++) {
        int i = tid + (it << 7);
        int c = i >> 4, e = (i & 15) << 2;
        *(float4*)&dst[c * LDW + e] = *(const float4*)&g_MT[(h << 12) + (c << 6) + e];
    }
}

__global__ __launch_bounds__(128, 4)
void disattn_kernel(const float* __restrict__ query,
                    const float* __restrict__ key_,
                    const float* __restrict__ value,
                    const float* __restrict__ Wv, const float* __restrict__ bv,
                    const float* __restrict__ Wu, const float* __restrict__ bu,
                    const float* __restrict__ Wr, const float* __restrict__ br,
                    float* __restrict__ out) {
    extern __shared__ float sm[];
    float* sA   = sm + O_A;     // MT / Wv / Wr staging
    float* sC   = sm + O_C;     // scores / attn
    float* sB   = sm + O_B;     // KMT then Vh
    float* mq   = sm + O_MQ;
    float* mqKM = sm + O_MQK;
    float* uV   = sm + O_UV;
    float* susm = sm + O_USM;

    const int tid = threadIdx.x;
    const int b = blockIdx.x;
    const int tx = tid & 15, ty = tid >> 4;
    const int R = ty << 3, C = tx << 2;

    const float* qg = query + (size_t)b * 4096;
    const float* kg = key_  + (size_t)b * 4096;
    const float* vg = value + (size_t)b * 4096;

    // Prologue: unary logits u[h][s] + query column means mq[e].
#pragma unroll
    for (int u = 0; u < 2; u++) {
        int slot = tid + (u << 7);
        int s = slot & 63, h = slot >> 6;
        const float* kr = kg + (s << 6);
        float acc = __ldg(&bu[h]);
#pragma unroll
        for (int cc = 0; cc < 16; cc++) {
            float4 kv = *(const float4*)&kr[cc << 2];
            acc = fmaf(kv.x, __ldg(&Wu[((cc << 2) + 0) * 4 + h]), acc);
            acc = fmaf(kv.y, __ldg(&Wu[((cc << 2) + 1) * 4 + h]), acc);
            acc = fmaf(kv.z, __ldg(&Wu[((cc << 2) + 2) * 4 + h]), acc);
            acc = fmaf(kv.w, __ldg(&Wu[((cc << 2) + 3) * 4 + h]), acc);
        }
        susm[(h << 6) + s] = acc;
    }
    if (tid < 64) {
        float s = 0.0f;
#pragma unroll
        for (int r = 0; r < 64; r++) s += qg[(r << 6) + tid];
        mq[tid] = s * (1.0f / 64.0f);
    }
    __syncthreads();

    // Unary softmax over fields s: warp w = head w.
    {
        int w = tid >> 5, lane = tid & 31;
        float v0 = susm[(w << 6) + lane];
        float v1 = susm[(w << 6) + 32 + lane];
        float m = fmaxf(v0, v1);
#pragma unroll
        for (int d = 16; d; d >>= 1)
            m = fmaxf(m, __shfl_xor_sync(0xffffffffu, m, d));
        float e0 = __expf(v0 - m), e1 = __expf(v1 - m);
        float s2 = e0 + e1;
#pragma unroll
        for (int d = 16; d; d >>= 1)
            s2 += __shfl_xor_sync(0xffffffffu, s2, d);
        float inv = 1.0f / s2;
        susm[(w << 6) + lane]      = e0 * inv;
        susm[(w << 6) + 32 + lane] = e1 * inv;
    }
    __syncthreads();

#pragma unroll 1
    for (int h = 0; h < 4; h++) {
        const int hc = h << 6;

        // a) stage MT_h
        stage_mt(sA, h, tid);
        __syncthreads();

        // b) KM = k @ MT (global A) -> transposed store KMT[e][t] into sB
        {
            float acc[8][4];
            init_tile(acc, 0.0f, 0.0f, 0.0f, 0.0f);
            gemm4(kg, 64, sA, LDW, acc, R, C);
#pragma unroll
            for (int j = 0; j < 4; j++)
#pragma unroll
                for (int i = 0; i < 8; i += 2)
                    *(float2*)&sB[(C + j) * LDKV + R + i] =
                        make_float2(acc[i][j], acc[i + 1][j]);
        }
        __syncthreads();

        // c) mqKM[t] = sum_e mq[e]*KMT[e][t]  (2 thr/t); stage Wv -> sA
        {
            int t = tid >> 1, e0 = (tid & 1) << 5;
            float s = 0.0f;
#pragma unroll
            for (int e = 0; e < 32; e++)
                s = fmaf(mq[e0 + e], sB[(e0 + e) * LDKV + t], s);
            s += __shfl_xor_sync(0xffffffffu, s, 1);
            if ((tid & 1) == 0) mqKM[t] = s;
        }
        stage_w(sA, Wv, hc, tid);
        __syncthreads();

        // d) scores = q @ KMT - mqKM (global A, float2 B) -> sC
        {
            float sacc[8][4];
            init_tile(sacc, -mqKM[C], -mqKM[C + 1], -mqKM[C + 2], -mqKM[C + 3]);
            gemm2(qg, 64, sB, LDKV, sacc, R, C);
            store_w(sC, sacc, R, C);
        }
        __syncthreads();

        // e) row softmax on sC (2 threads/row, rotated float4), no unary add
        {
            int row = tid >> 1, half = tid & 1;
            float* sr = &sC[row * LDW + (half << 5)];
            int rot = row & 7;
            float4 v[8];
#pragma unroll
            for (int cc = 0; cc < 8; cc++) {
                int c4 = ((cc + rot) & 7) << 2;
                v[cc] = *(const float4*)&sr[c4];
            }
            float m = -1e30f;
#pragma unroll
            for (int cc = 0; cc < 8; cc++)
                m = fmaxf(m, fmaxf(fmaxf(v[cc].x, v[cc].y), fmaxf(v[cc].z, v[cc].w)));
            m = fmaxf(m, __shfl_xor_sync(0xffffffffu, m, 1));
            float ssum = 0.0f;
#pragma unroll
            for (int cc = 0; cc < 8; cc++) {
                v[cc].x = __expf(v[cc].x - m);
                v[cc].y = __expf(v[cc].y - m);
                v[cc].z = __expf(v[cc].z - m);
                v[cc].w = __expf(v[cc].w - m);
                ssum += v[cc].x + v[cc].y + v[cc].z + v[cc].w;
            }
            ssum += __shfl_xor_sync(0xffffffffu, ssum, 1);
            float inv = 1.0f / ssum;
#pragma unroll
            for (int cc = 0; cc < 8; cc++) {
                int c4 = ((cc + rot) & 7) << 2;
                v[cc].x *= inv; v[cc].y *= inv; v[cc].z *= inv; v[cc].w *= inv;
                *(float4*)&sr[c4] = v[cc];
            }
        }
        __syncthreads();

        // f) Vh = v @ Wv + bv (global A) -> sB (KMT dead), float2 stores
        {
            float acc[8][4];
            init_tile(acc, __ldg(&bv[hc + C]), __ldg(&bv[hc + C + 1]),
                      __ldg(&bv[hc + C + 2]), __ldg(&bv[hc + C + 3]));
            gemm4(vg, 64, sA, LDW, acc, R, C);
#pragma unroll
            for (int i = 0; i < 8; i++) {
                *(float2*)&sB[(R + i) * LDKV + C]     = make_float2(acc[i][0], acc[i][1]);
                *(float2*)&sB[(R + i) * LDKV + C + 2] = make_float2(acc[i][2], acc[i][3]);
            }
        }
        __syncthreads();

        // g) uV[c] = sum_t u[t]*Vh[t][c]  (2 thr/c); stage Wr -> sA
        {
            int c = tid >> 1, t0 = (tid & 1) << 5;
            float s = 0.0f;
#pragma unroll
            for (int t = 0; t < 32; t++)
                s = fmaf(susm[hc + t0 + t], sB[(t0 + t) * LDKV + c], s);
            s += __shfl_xor_sync(0xffffffffu, s, 1);
            if ((tid & 1) == 0) uV[c] = s;
        }
        stage_w(sA, Wr, hc, tid);
        __syncthreads();

        // h) out = attn @ Vh + q @ Wr + br + uV
        {
            float acc[8][4];
            init_tile(acc,
                      __ldg(&br[hc + C])     + uV[C],
                      __ldg(&br[hc + C + 1]) + uV[C + 1],
                      __ldg(&br[hc + C + 2]) + uV[C + 2],
                      __ldg(&br[hc + C + 3]) + uV[C + 3]);
            gemm2(sC, LDW, sB, LDKV, acc, R, C);   // attn @ Vh
            gemm4(qg, 64, sA, LDW, acc, R, C);     // q @ Wr

            float* og = out + (size_t)b * 16384 + R * 256 + hc + C;
#pragma unroll
            for (int i = 0; i < 8; i++)
                *(float4*)&og[i * 256] =
                    make_float4(acc[i][0], acc[i][1], acc[i][2], acc[i][3]);
        }
        __syncthreads();
    }
}

extern "C" void kernel_launch(void* const* d_in, const int* in_sizes, int n_in,
                              void* d_out, int out_size) {
    const float* query = (const float*)d_in[0];
    const float* key_  = (const float*)d_in[1];
    const float* value = (const float*)d_in[2];
    const float* Wq    = (const float*)d_in[3];
    const float* Wk    = (const float*)d_in[5];
    const float* Wv    = (const float*)d_in[7];
    const float* bv    = (const float*)d_in[8];
    const float* Wu    = (const float*)d_in[9];
    const float* bu    = (const float*)d_in[10];
    const float* Wr    = (const float*)d_in[11];
    const float* br    = (const float*)d_in[12];
    float* out = (float*)d_out;

    precompute_MT<<<4, 256>>>(Wq, Wk);

    size_t smem = SM_FLOATS * sizeof(float);   // 53504 B -> 4 CTAs/SM
    cudaFuncSetAttribute(disattn_kernel,
                         cudaFuncAttributeMaxDynamicSharedMemorySize, (int)smem);
    disattn_kernel<<<4096, 128, smem>>>(query, key_, value, Wv, bv,
                                        Wu, bu, Wr, br, out);
}

// round 16
// speedup vs baseline: 1.4298x; 1.4298x over previous
#include <cuda_runtime.h>
#include <cstdint>

// Hybrid FFMA + tf32 mma.sync. 1 batch/CTA, grid 4096, 128 thr, 54.3KB smem
// -> 4 CTAs/SM. FFMA fp32: QM=q@M, S=QM@kT (softmax chain). tf32 tensor:
// Vh=v@Wv+bv, out=attn@Vh + q@Wr. Centering = subtract column-mean of raw S
// (exact: mean_s(q@M@kT) = mq@M@kT). bq/bk cancel. unary is rank-1 -> epilogue.
// Precompute: g_M[h][e][f] = (Wq_h@Wk_h^T)[e][f]; g_Wvt/g_Wrt tf32-rounded.

#define LKT 66
#define LW  68
#define LVH 72
#define O_KT  0
#define O_W   4224
#define O_VH  8576
#define O_USM 13184
#define O_CM  13440
#define O_UV  13504
#define SM_FLOATS 13568   // 54272 B

__device__ float g_M[4 * 64 * 64];
__device__ float g_Wvt[64 * 256];
__device__ float g_Wrt[64 * 256];

__device__ __forceinline__ uint32_t f2tf(float x) {
    uint32_t r;
    asm("cvt.rna.tf32.f32 %0, %1;" : "=r"(r) : "f"(x));
    return r;
}
__device__ __forceinline__ void mma8(float c[4], uint32_t a0, uint32_t a1,
                                     uint32_t a2, uint32_t a3,
                                     uint32_t b0, uint32_t b1) {
    asm("mma.sync.aligned.m16n8k8.row.col.f32.tf32.tf32.f32 "
        "{%0,%1,%2,%3},{%4,%5,%6,%7},{%8,%9},{%0,%1,%2,%3};"
        : "+f"(c[0]), "+f"(c[1]), "+f"(c[2]), "+f"(c[3])
        : "r"(a0), "r"(a1), "r"(a2), "r"(a3), "r"(b0), "r"(b1));
}

__global__ __launch_bounds__(256) void precompute(const float* __restrict__ Wq,
                                                  const float* __restrict__ Wk,
                                                  const float* __restrict__ Wv,
                                                  const float* __restrict__ Wr) {
    const int tid = threadIdx.x;
    if (blockIdx.x < 4) {
        __shared__ float sq[64 * 68], sk[64 * 68];
        const int h = blockIdx.x, hc = h << 6;
#pragma unroll
        for (int it = 0; it < 4; it++) {
            int i = tid + (it << 8);
            int e = i >> 4, a = (i & 15) << 2;
            *(float4*)&sq[e * 68 + a] = *(const float4*)&Wq[(e << 8) + hc + a];
            *(float4*)&sk[e * 68 + a] = *(const float4*)&Wk[(e << 8) + hc + a];
        }
        __syncthreads();
#pragma unroll
        for (int it = 0; it < 16; it++) {
            int idx = tid + (it << 8);
            int e = idx >> 6, f = idx & 63;
            float acc = 0.0f;
#pragma unroll
            for (int a = 0; a < 64; a += 4) {
                float4 qa = *(const float4*)&sq[e * 68 + a];
                float4 ka = *(const float4*)&sk[f * 68 + a];
                acc = fmaf(qa.x, ka.x, acc);
                acc = fmaf(qa.y, ka.y, acc);
                acc = fmaf(qa.z, ka.z, acc);
                acc = fmaf(qa.w, ka.w, acc);
            }
            g_M[(h << 12) + (e << 6) + f] = acc;
        }
    } else {
        int base = (blockIdx.x - 4) << 12;
#pragma unroll
        for (int it = 0; it < 16; it++) {
            int i = base + tid + (it << 8);
            g_Wvt[i] = __uint_as_float(f2tf(Wv[i]));
            g_Wrt[i] = __uint_as_float(f2tf(Wr[i]));
        }
    }
}

// FFMA: A (global/smem, stride lda) x B (smem, stride ldb, float4 reads)
__device__ __forceinline__ void gemm4(const float* __restrict__ A, int lda,
                                      const float* __restrict__ B, int ldb,
                                      float acc[8][4], int R, int C) {
#pragma unroll
    for (int k = 0; k < 64; k += 4) {
        float4 a[8];
#pragma unroll
        for (int i = 0; i < 8; i++) a[i] = *(const float4*)&A[(R + i) * lda + k];
#pragma unroll
        for (int kk = 0; kk < 4; kk++) {
            float4 b4 = *(const float4*)&B[(k + kk) * ldb + C];
#pragma unroll
            for (int i = 0; i < 8; i++) {
                float av = (kk == 0) ? a[i].x : (kk == 1) ? a[i].y
                         : (kk == 2) ? a[i].z : a[i].w;
                acc[i][0] = fmaf(av, b4.x, acc[i][0]);
                acc[i][1] = fmaf(av, b4.y, acc[i][1]);
                acc[i][2] = fmaf(av, b4.z, acc[i][2]);
                acc[i][3] = fmaf(av, b4.w, acc[i][3]);
            }
        }
    }
}

// FFMA: B float2 reads (ldb even)
__device__ __forceinline__ void gemm2(const float* __restrict__ A, int lda,
                                      const float* __restrict__ B, int ldb,
                                      float acc[8][4], int R, int C) {
#pragma unroll
    for (int k = 0; k < 64; k += 4) {
        float4 a[8];
#pragma unroll
        for (int i = 0; i < 8; i++) a[i] = *(const float4*)&A[(R + i) * lda + k];
#pragma unroll
        for (int kk = 0; kk < 4; kk++) {
            float2 bl = *(const float2*)&B[(k + kk) * ldb + C];
            float2 bh = *(const float2*)&B[(k + kk) * ldb + C + 2];
#pragma unroll
            for (int i = 0; i < 8; i++) {
                float av = (kk == 0) ? a[i].x : (kk == 1) ? a[i].y
                         : (kk == 2) ? a[i].z : a[i].w;
                acc[i][0] = fmaf(av, bl.x, acc[i][0]);
                acc[i][1] = fmaf(av, bl.y, acc[i][1]);
                acc[i][2] = fmaf(av, bh.x, acc[i][2]);
                acc[i][3] = fmaf(av, bh.y, acc[i][3]);
            }
        }
    }
}

__global__ __launch_bounds__(128, 4)
void disattn_kernel(const float* __restrict__ query,
                    const float* __restrict__ key_,
                    const float* __restrict__ value,
                    const float* __restrict__ bv,
                    const float* __restrict__ Wu, const float* __restrict__ bu,
                    const float* __restrict__ br,
                    float* __restrict__ out) {
    extern __shared__ float sm[];
    float* sKT  = sm + O_KT;    // [64][66] kT, resident all heads
    float* sW   = sm + O_W;     // [64][68] M -> QM -> scores -> attn
    float* sVh  = sm + O_VH;    // [64][72] Vh (tf32-rounded values)
    float* susm = sm + O_USM;   // [4][64]
    float* cm   = sm + O_CM;    // [64] score column means
    float* uV   = sm + O_UV;    // [64]

    const int tid = threadIdx.x;
    const int b = blockIdx.x;
    const int tx = tid & 15, ty = tid >> 4;
    const int R = ty << 3, C = tx << 2;
    const int lane = tid & 31, warp = tid >> 5;
    const int m0 = warp << 4;
    const int fr = lane >> 2, fc = lane & 3;

    const float* qg = query + (size_t)b * 4096;
    const float* kg = key_  + (size_t)b * 4096;
    const float* vg = value + (size_t)b * 4096;

    // Prologue: unary logits; stage kT.
#pragma unroll
    for (int u = 0; u < 2; u++) {
        int slot = tid + (u << 7);
        int s = slot & 63, h = slot >> 6;
        const float* kr = kg + (s << 6);
        float acc = __ldg(&bu[h]);
#pragma unroll
        for (int cc = 0; cc < 16; cc++) {
            float4 kv = *(const float4*)&kr[cc << 2];
            acc = fmaf(kv.x, __ldg(&Wu[((cc << 2) + 0) * 4 + h]), acc);
            acc = fmaf(kv.y, __ldg(&Wu[((cc << 2) + 1) * 4 + h]), acc);
            acc = fmaf(kv.z, __ldg(&Wu[((cc << 2) + 2) * 4 + h]), acc);
            acc = fmaf(kv.w, __ldg(&Wu[((cc << 2) + 3) * 4 + h]), acc);
        }
        susm[(h << 6) + s] = acc;
    }
    {
        int t = tid & 63, half = tid >> 6;      // kT[f][t] = k[t][f]
        const float* kr = kg + (t << 6) + (half << 5);
#pragma unroll
        for (int j = 0; j < 32; j += 4) {
            float4 kv = *(const float4*)&kr[j];
            int f = (half << 5) + j;
            sKT[(f + 0) * LKT + t] = kv.x;
            sKT[(f + 1) * LKT + t] = kv.y;
            sKT[(f + 2) * LKT + t] = kv.z;
            sKT[(f + 3) * LKT + t] = kv.w;
        }
    }
    __syncthreads();

    // Unary softmax over fields: warp w = head w.
    {
        float v0 = susm[(warp << 6) + lane];
        float v1 = susm[(warp << 6) + 32 + lane];
        float m = fmaxf(v0, v1);
#pragma unroll
        for (int d = 16; d; d >>= 1)
            m = fmaxf(m, __shfl_xor_sync(0xffffffffu, m, d));
        float e0 = __expf(v0 - m), e1 = __expf(v1 - m);
        float s2 = e0 + e1;
#pragma unroll
        for (int d = 16; d; d >>= 1)
            s2 += __shfl_xor_sync(0xffffffffu, s2, d);
        float inv = 1.0f / s2;
        susm[(warp << 6) + lane]      = e0 * inv;
        susm[(warp << 6) + 32 + lane] = e1 * inv;
    }
    __syncthreads();

#pragma unroll 1
    for (int h = 0; h < 4; h++) {
        const int hc = h << 6;
        const float* Mh = &g_M[h << 12];

        // 1) stage M_h -> sW
#pragma unroll
        for (int it = 0; it < 8; it++) {
            int i = tid + (it << 7);
            int e = i >> 4, f = (i & 15) << 2;
            *(float4*)&sW[e * LW + f] = *(const float4*)&Mh[(e << 6) + f];
        }
        __syncthreads();

        // 2) QM = q @ M (FFMA, global A); sync; overwrite own rows with QM
        {
            float acc[8][4];
#pragma unroll
            for (int i = 0; i < 8; i++)
                acc[i][0] = acc[i][1] = acc[i][2] = acc[i][3] = 0.0f;
            gemm4(qg, 64, sW, LW, acc, R, C);
            __syncthreads();                 // all warps done reading M
#pragma unroll
            for (int i = 0; i < 8; i++)
                *(float4*)&sW[(R + i) * LW + C] =
                    make_float4(acc[i][0], acc[i][1], acc[i][2], acc[i][3]);
        }
        __syncwarp();

        // 3) S = QM @ kT (FFMA; A rows warp-private, B=sKT stable).
        {
            float acc[8][4];
#pragma unroll
            for (int i = 0; i < 8; i++)
                acc[i][0] = acc[i][1] = acc[i][2] = acc[i][3] = 0.0f;
            gemm2(sW, LW, sKT, LKT, acc, R, C);
#pragma unroll
            for (int i = 0; i < 8; i++)      // overwrite own QM rows with S
                *(float4*)&sW[(R + i) * LW + C] =
                    make_float4(acc[i][0], acc[i][1], acc[i][2], acc[i][3]);
        }
        __syncthreads();

        // 4) column means of raw S (== centering shift), 2 thr/col
        {
            int t = tid >> 1, s0 = (tid & 1) << 5;
            float s = 0.0f;
#pragma unroll
            for (int r = 0; r < 32; r++) s += sW[(s0 + r) * LW + t];
            s += __shfl_xor_sync(0xffffffffu, s, 1);
            if ((tid & 1) == 0) cm[t] = s * (1.0f / 64.0f);
        }
        __syncthreads();

        // 5) row softmax (2 thr/row, rotated float4, subtract cm)
        {
            int row = tid >> 1, half = tid & 1;
            float* sr = &sW[row * LW + (half << 5)];
            const float* cmh = &cm[half << 5];
            int rot = row & 7;
            float4 v[8];
#pragma unroll
            for (int cc = 0; cc < 8; cc++) {
                int c4 = ((cc + rot) & 7) << 2;
                float4 x = *(const float4*)&sr[c4];
                float4 c4m = *(const float4*)&cmh[c4];
                v[cc] = make_float4(x.x - c4m.x, x.y - c4m.y,
                                    x.z - c4m.z, x.w - c4m.w);
            }
            float m = -1e30f;
#pragma unroll
            for (int cc = 0; cc < 8; cc++)
                m = fmaxf(m, fmaxf(fmaxf(v[cc].x, v[cc].y), fmaxf(v[cc].z, v[cc].w)));
            m = fmaxf(m, __shfl_xor_sync(0xffffffffu, m, 1));
            float ssum = 0.0f;
#pragma unroll
            for (int cc = 0; cc < 8; cc++) {
                v[cc].x = __expf(v[cc].x - m);
                v[cc].y = __expf(v[cc].y - m);
                v[cc].z = __expf(v[cc].z - m);
                v[cc].w = __expf(v[cc].w - m);
                ssum += v[cc].x + v[cc].y + v[cc].z + v[cc].w;
            }
            ssum += __shfl_xor_sync(0xffffffffu, ssum, 1);
            float inv = 1.0f / ssum;
#pragma unroll
            for (int cc = 0; cc < 8; cc++) {
                int c4 = ((cc + rot) & 7) << 2;
                v[cc].x *= inv; v[cc].y *= inv; v[cc].z *= inv; v[cc].w *= inv;
                *(float4*)&sr[c4] = v[cc];
            }
        }
        __syncwarp();   // attn rows are warp-private from here

        // 6) Vh = v @ Wv + bv  (tf32 mma, A global, B table) -> sVh rows m0..15
        {
            float acc[8][4];
#pragma unroll
            for (int nb = 0; nb < 8; nb++) {
                float b0 = __ldg(&bv[hc + (nb << 3) + (fc << 1)]);
                float b1 = __ldg(&bv[hc + (nb << 3) + (fc << 1) + 1]);
                acc[nb][0] = b0; acc[nb][1] = b1;
                acc[nb][2] = b0; acc[nb][3] = b1;
            }
#pragma unroll
            for (int kb = 0; kb < 8; kb++) {
                int k0 = kb << 3;
                uint32_t a0 = f2tf(__ldg(&vg[(m0 + fr) * 64 + k0 + fc]));
                uint32_t a1 = f2tf(__ldg(&vg[(m0 + fr + 8) * 64 + k0 + fc]));
                uint32_t a2 = f2tf(__ldg(&vg[(m0 + fr) * 64 + k0 + fc + 4]));
                uint32_t a3 = f2tf(__ldg(&vg[(m0 + fr + 8) * 64 + k0 + fc + 4]));
#pragma unroll
                for (int nb = 0; nb < 8; nb++) {
                    uint32_t b0 = __float_as_uint(
                        __ldg(&g_Wvt[(k0 + fc) * 256 + hc + (nb << 3) + fr]));
                    uint32_t b1 = __float_as_uint(
                        __ldg(&g_Wvt[(k0 + fc + 4) * 256 + hc + (nb << 3) + fr]));
                    mma8(acc[nb], a0, a1, a2, a3, b0, b1);
                }
            }
#pragma unroll
            for (int nb = 0; nb < 8; nb++) {   // store tf32-rounded
                int n = (nb << 3) + (fc << 1);
                *(float2*)&sVh[(m0 + fr) * LVH + n] = make_float2(
                    __uint_as_float(f2tf(acc[nb][0])),
                    __uint_as_float(f2tf(acc[nb][1])));
                *(float2*)&sVh[(m0 + fr + 8) * LVH + n] = make_float2(
                    __uint_as_float(f2tf(acc[nb][2])),
                    __uint_as_float(f2tf(acc[nb][3])));
            }
        }
        __syncthreads();

        // 7) uV[c] = unary @ Vh  (2 thr/col)
        {
            int c = tid >> 1, t0 = (tid & 1) << 5;
            float s = 0.0f;
#pragma unroll
            for (int t = 0; t < 32; t++)
                s = fmaf(susm[hc + t0 + t], sVh[(t0 + t) * LVH + c], s);
            s += __shfl_xor_sync(0xffffffffu, s, 1);
            if ((tid & 1) == 0) uV[c] = s;
        }
        __syncthreads();

        // 8) out = attn@Vh + q@Wr + br + uV  (tf32 mma)
        {
            float acc[8][4];
#pragma unroll
            for (int nb = 0; nb < 8; nb++) {
                int n = (nb << 3) + (fc << 1);
                float b0 = __ldg(&br[hc + n])     + uV[n];
                float b1 = __ldg(&br[hc + n + 1]) + uV[n + 1];
                acc[nb][0] = b0; acc[nb][1] = b1;
                acc[nb][2] = b0; acc[nb][3] = b1;
            }
#pragma unroll
            for (int kb = 0; kb < 8; kb++) {     // attn @ Vh (smem A, smem B)
                int k0 = kb << 3;
                uint32_t a0 = f2tf(sW[(m0 + fr) * LW + k0 + fc]);
                uint32_t a1 = f2tf(sW[(m0 + fr + 8) * LW + k0 + fc]);
                uint32_t a2 = f2tf(sW[(m0 + fr) * LW + k0 + fc + 4]);
                uint32_t a3 = f2tf(sW[(m0 + fr + 8) * LW + k0 + fc + 4]);
#pragma unroll
                for (int nb = 0; nb < 8; nb++) {
                    uint32_t b0 = __float_as_uint(sVh[(k0 + fc) * LVH + (nb << 3) + fr]);
                    uint32_t b1 = __float_as_uint(sVh[(k0 + fc + 4) * LVH + (nb << 3) + fr]);
                    mma8(acc[nb], a0, a1, a2, a3, b0, b1);
                }
            }
#pragma unroll
            for (int kb = 0; kb < 8; kb++) {     // q @ Wr (global A, table B)
                int k0 = kb << 3;
                uint32_t a0 = f2tf(__ldg(&qg[(m0 + fr) * 64 + k0 + fc]));
                uint32_t a1 = f2tf(__ldg(&qg[(m0 + fr + 8) * 64 + k0 + fc]));
                uint32_t a2 = f2tf(__ldg(&qg[(m0 + fr) * 64 + k0 + fc + 4]));
                uint32_t a3 = f2tf(__ldg(&qg[(m0 + fr + 8) * 64 + k0 + fc + 4]));
#pragma unroll
                for (int nb = 0; nb < 8; nb++) {
                    uint32_t b0 = __float_as_uint(
                        __ldg(&g_Wrt[(k0 + fc) * 256 + hc + (nb << 3) + fr]));
                    uint32_t b1 = __float_as_uint(
                        __ldg(&g_Wrt[(k0 + fc + 4) * 256 + hc + (nb << 3) + fr]));
                    mma8(acc[nb], a0, a1, a2, a3, b0, b1);
                }
            }
            float* og = out + (size_t)b * 16384 + hc;
#pragma unroll
            for (int nb = 0; nb < 8; nb++) {
                int n = (nb << 3) + (fc << 1);
                *(float2*)&og[(m0 + fr) * 256 + n] = make_float2(acc[nb][0], acc[nb][1]);
                *(float2*)&og[(m0 + fr + 8) * 256 + n] = make_float2(acc[nb][2], acc[nb][3]);
            }
        }
        __syncthreads();   // sW/sVh reused next head
    }
}

extern "C" void kernel_launch(void* const* d_in, const int* in_sizes, int n_in,
                              void* d_out, int out_size) {
    const float* query = (const float*)d_in[0];
    const float* key_  = (const float*)d_in[1];
    const float* value = (const float*)d_in[2];
    const float* Wq    = (const float*)d_in[3];
    const float* Wk    = (const float*)d_in[5];
    const float* Wv    = (const float*)d_in[7];
    const float* bv    = (const float*)d_in[8];
    const float* Wu    = (const float*)d_in[9];
    const float* bu    = (const float*)d_in[10];
    const float* Wr    = (const float*)d_in[11];
    const float* br    = (const float*)d_in[12];
    float* out = (float*)d_out;

    precompute<<<8, 256>>>(Wq, Wk, Wv, Wr);

    size_t smem = SM_FLOATS * sizeof(float);   // 54272 B -> 4 CTAs/SM
    cudaFuncSetAttribute(disattn_kernel,
                         cudaFuncAttributeMaxDynamicSharedMemorySize, (int)smem);
    disattn_kernel<<<4096, 128, smem>>>(query, key_, value, bv,
                                        Wu, bu, br, out);
}